// round 1
// baseline (speedup 1.0000x reference)
#include <cuda_runtime.h>
#include <stdint.h>

// out[b,i,j,:] = pe[clamp(128 + j - i, 0, 256), :]
// B=4, S=512, D=128, pe is [512,128] fp32 (only rows 0..256 referenced).
//
// One warp per output row of 128 floats: lane l handles floats [4l, 4l+4).
// pe working set = 257 * 512B = ~131 KB -> resident in L1 after warm-up,
// so the kernel is bound purely by the 512 MB of HBM stores.

__global__ __launch_bounds__(256) void relpos_kernel(
    const float4* __restrict__ pe,   // [512][32] float4
    float4* __restrict__ out,        // [n_rows][32] float4
    int n_rows)                      // B*S*S
{
    int gtid = blockIdx.x * blockDim.x + threadIdx.x;
    int warp = gtid >> 5;
    int lane = gtid & 31;
    if (warp >= n_rows) return;

    // warp -> (b, i, j); b unused (broadcast), layout is row-major [B,S,S,D]
    int j = warp & 511;
    int i = (warp >> 9) & 511;

    int rel = 128 + j - i;
    rel = rel < 0 ? 0 : (rel > 256 ? 256 : rel);

    // coalesced 512B row read (L1-resident) + coalesced 512B row write
    out[(size_t)warp * 32 + lane] = pe[rel * 32 + lane];
}

extern "C" void kernel_launch(void* const* d_in, const int* in_sizes, int n_in,
                              void* d_out, int out_size)
{
    // d_in[0] = x (int32 [4,512], shape-only), d_in[1] = pe (float32 [512,128])
    const float4* pe = (const float4*)d_in[1];
    float4* out = (float4*)d_out;

    int n_rows = out_size >> 7;           // out_size / 128 = B*S*S
    int n_threads = n_rows * 32;
    int block = 256;
    int grid = (n_threads + block - 1) / block;

    relpos_kernel<<<grid, block>>>(pe, out, n_rows);
}